// round 17
// baseline (speedup 1.0000x reference)
#include <cuda_runtime.h>
#include <cuda_fp16.h>
#include <cstdint>

// ============================================================================
// TensorTrain forward, MEGAKERNEL edition.
//   pack_core: cores -> packed fp16 A blocks (x64 scaled)     [launch 1]
//   mega (grid 128, one CTA per 32-col n-strip):              [launch 2]
//     v3 = core3 @ X2        (smem)
//     u2 = contract(perm(core2) @ X1, v3)   (GEMM pass 0, B resident)
//     u1 = contract(perm(core1) @ X0, u2)   (GEMM pass 1)
//     Z  = core0 @ u1        (written to gmem)
//
// GEMM per CTA: M=1024 (16 warps x 64 rows), N=32, K=512.
// A streams as BK=16 stages (1024 x 48B rows, 3 stages, wait_group 1).
// B resident: 16 sub-tiles [32 rows x 80B] converted from fp32 X in-kernel.
// A fp16 pre-scaled x64; epilogues multiply by 1/64. f32 accum everywhere.
//
// Packed A layout per (mt, kc=32k) block of 2048 u32 words (dense):
//   word[m_loc*16 + kp] = f16pair(A[m][2kp], A[m][2kp+1]).
// SMEM A rows 48B (3 coprime 8 -> ldsm conflict-free), B rows 80B (5 coprime 8).
// __device__ globals only referenced from device code.
// ============================================================================

namespace {
constexpr int NB = 4096;
constexpr int D  = 512;
constexpr int R  = 32;
constexpr float ASCALE  = 64.f;
constexpr float UNSCALE = 1.f / 64.f;
// mega smem (bytes)
constexpr int SM_B   = 0;                    // 16 x 2560 = 40960
constexpr int SM_A   = 40960;                // 3 stages x 49152 = 147456
constexpr int A_STG  = 49152;                // 1024 rows x 48 B
constexpr int SM_U0  = 188416;               // scale-in  32 x 33 f32 = 4224
constexpr int SM_U1  = 192640;               // u-out     32 x 33 f32 = 4224
constexpr int SM_TOTAL_MEGA = 196864;
}

__device__ uint32_t g_A1[8 * 16 * 2048];
__device__ uint32_t g_A2[8 * 16 * 2048];

// ---------------------------------------------------------------------------
__device__ __forceinline__ uint32_t smem_u32(const void* p) {
    uint32_t a;
    asm("{ .reg .u64 t; cvta.to.shared.u64 t, %1; cvt.u32.u64 %0, t; }" : "=r"(a) : "l"(p));
    return a;
}
__device__ __forceinline__ void cp16(uint32_t saddr, const void* g) {
    asm volatile("cp.async.cg.shared.global [%0], [%1], 16;" :: "r"(saddr), "l"(g) : "memory");
}
#define CP_COMMIT() asm volatile("cp.async.commit_group;" ::: "memory")

__device__ __forceinline__ void mma16816(float* d, const uint32_t* a, const uint32_t* b) {
    asm volatile(
        "mma.sync.aligned.m16n8k16.row.col.f32.f16.f16.f32 "
        "{%0,%1,%2,%3}, {%4,%5,%6,%7}, {%8,%9}, {%0,%1,%2,%3};"
        : "+f"(d[0]), "+f"(d[1]), "+f"(d[2]), "+f"(d[3])
        : "r"(a[0]), "r"(a[1]), "r"(a[2]), "r"(a[3]), "r"(b[0]), "r"(b[1]));
}
__device__ __forceinline__ void ldsm4(uint32_t* r, uint32_t saddr) {
    asm volatile("ldmatrix.sync.aligned.m8n8.x4.shared.b16 {%0,%1,%2,%3}, [%4];"
                 : "=r"(r[0]), "=r"(r[1]), "=r"(r[2]), "=r"(r[3]) : "r"(saddr));
}
__device__ __forceinline__ uint32_t h2pack(__half a, __half b) {
    return ((uint32_t)__half_as_ushort(b) << 16) | __half_as_ushort(a);
}
__device__ __forceinline__ uint32_t pack_af(float x0, float x1) {
    return h2pack(__float2half_rn(x0 * ASCALE), __float2half_rn(x1 * ASCALE));
}
__device__ __forceinline__ uint32_t pack_bf(float x0, float x1) {
    return h2pack(__float2half_rn(x0), __float2half_rn(x1));
}

// ---------------------------------------------------------------------------
// Pack both cores -> A blocks (dense). grid (mt=8, kc=16, z=2), 256 thr.
// ---------------------------------------------------------------------------
__global__ __launch_bounds__(256)
void pack_core_kernel(const float* __restrict__ c1, const float* __restrict__ c2)
{
    const float* __restrict__ core = (blockIdx.z == 0) ? c1 : c2;
    uint32_t* __restrict__ out     = (blockIdx.z == 0) ? g_A1 : g_A2;
    __shared__ float sC[4 * 1056];    // [a_loc][kloc(32) stride 33][b(32)]
    const int t = threadIdx.x, mt = blockIdx.x, kc = blockIdx.y;
#pragma unroll
    for (int i = 0; i < 16; i++) {
        int idx = t + i * 256;                 // 0..4095
        int a_loc = idx >> 10, rem = idx & 1023;
        int kloc = rem >> 5, b = rem & 31;
        sC[a_loc * 1056 + kloc * 33 + b] =
            core[(mt * 4 + a_loc) * (D * R) + kc * 1024 + rem];
    }
    __syncthreads();
    uint32_t* dst = out + (mt * 16 + kc) * 2048;
#pragma unroll
    for (int i = 0; i < 8; i++) {
        int w = t + i * 256;                   // 0..2047
        int m_loc = w >> 4, kp = w & 15;
        int a_loc = m_loc >> 5, b = m_loc & 31, k0 = kp * 2;
        float x0 = sC[a_loc * 1056 + k0 * 33 + b];
        float x1 = sC[a_loc * 1056 + (k0 + 1) * 33 + b];
        dst[w] = pack_af(x0, x1);
    }
}

// ---------------------------------------------------------------------------
// MEGAKERNEL. grid 128 CTAs (nc -> cols nc*32..+31), 512 threads / 16 warps.
// ---------------------------------------------------------------------------
__global__ __launch_bounds__(512, 1)
void mega_kernel(const float* __restrict__ X0, const float* __restrict__ X1,
                 const float* __restrict__ X2, const float* __restrict__ core0,
                 const float* __restrict__ core3, float* __restrict__ Z)
{
    extern __shared__ char smem[];
    const int t = threadIdx.x, warp = t >> 5, lane = t & 31;
    const int g = lane >> 2, c = lane & 3;
    const int nc = blockIdx.x, n0 = nc * 32;
    const uint32_t sbase = smem_u32(smem);

    const int mat  = lane >> 3;          // 0..3
    const int mrow = lane & 7;
    const int hA = mat >> 1;             // A k-half (16B group within k16)
    const int hB = mat & 1;              // B k-half
    // A frag base: rows 64*warp + 16i + (mat&1)*8 + mrow, 48B stride
    const uint32_t aOff = (uint32_t)(64 * warp + (mat & 1) * 8 + mrow) * 48 + hA * 16;
    // B frag base: rows (mat>>1)*8 + mrow (+jp*8), 80B stride
    const uint32_t bOff = (uint32_t)((mat >> 1) * 8 + mrow) * 80 + hB * 16;

    float* sXf = (float*)(smem + SM_A);            // fp32 staging (X / X2 / core0)
    float* sC3 = (float*)(smem + SM_A + 67584);    // core3 staging
    uint32_t* sBw = (uint32_t*)(smem + SM_B);
    float* sU0 = (float*)(smem + SM_U0);
    float* sU1 = (float*)(smem + SM_U1);

    // ---- v3[b, nl] = sum_d core3[b,d] * X2[d, n0+nl] -> sU0 ----
    {
#pragma unroll
        for (int i = 0; i < 32; i++) {
            int idx = t + i * 512;                 // 16384 X2 floats
            sXf[(idx >> 5) * 33 + (idx & 31)] = X2[(idx >> 5) * NB + n0 + (idx & 31)];
        }
#pragma unroll
        for (int i = 0; i < 32; i++) {
            int idx = t + i * 512;                 // 16384 core3 floats
            sC3[idx] = core3[idx];
        }
        __syncthreads();
        const int b = t >> 4, ncp = (t & 15) * 2;
        float a0 = 0.f, a1 = 0.f;
#pragma unroll 8
        for (int d = 0; d < 512; d++) {
            float cv = sC3[b * 512 + d];
            a0 += cv * sXf[d * 33 + ncp];
            a1 += cv * sXf[d * 33 + ncp + 1];
        }
        sU0[b * 33 + ncp]     = a0;
        sU0[b * 33 + ncp + 1] = a1;
        __syncthreads();
    }

    // ---- two fused GEMM+contract passes ----
    for (int pass = 0; pass < 2; pass++) {
        const uint32_t* __restrict__ Apk = (pass == 0) ? g_A2 : g_A1;
        const float*    __restrict__ X   = (pass == 0) ? X1 : X0;

        // stage X fp32 (coalesced), convert to resident fp16 B tiles
#pragma unroll
        for (int i = 0; i < 32; i++) {
            int idx = t + i * 512;
            sXf[(idx >> 5) * 33 + (idx & 31)] = X[(idx >> 5) * NB + n0 + (idx & 31)];
        }
        __syncthreads();
#pragma unroll
        for (int i = 0; i < 16; i++) {
            int w = t + i * 512;                   // 8192 B words
            int sub = w >> 9, rem = w & 511;
            int row = rem >> 4, kp = rem & 15;
            int k = sub * 32 + kp * 2;
            sBw[sub * 640 + row * 20 + kp] =
                pack_bf(sXf[k * 33 + row], sXf[(k + 1) * 33 + row]);
        }
        __syncthreads();

        float acc[4][4][4];
#pragma unroll
        for (int i = 0; i < 4; i++)
#pragma unroll
            for (int j = 0; j < 4; j++)
#pragma unroll
                for (int q = 0; q < 4; q++) acc[i][j][q] = 0.f;

        // A stage issue: stage s covers k16 index s (BK=16). 4 cp16/thread.
        auto issueA = [&](int s) {
            uint32_t sd = sbase + SM_A + (s % 3) * A_STG;
            const uint32_t* blk = Apk + (s >> 1) * 2048 + (s & 1) * 8;
#pragma unroll
            for (int i = 0; i < 4; i++) {
                int ch = t + i * 512;              // 0..2047
                int row = ch >> 1, half = ch & 1;
                int mt = row >> 7, m_loc = row & 127;
                cp16(sd + (uint32_t)row * 48 + half * 16,
                     blk + mt * 16 * 2048 + m_loc * 16 + half * 4);
            }
            CP_COMMIT();
        };
        issueA(0);
        issueA(1);

        for (int kq = 0; kq < 32; kq++) {
            if (kq < 31)
                asm volatile("cp.async.wait_group 1;" ::: "memory");
            else
                asm volatile("cp.async.wait_group 0;" ::: "memory");
            __syncthreads();
            if (kq + 2 < 32) issueA(kq + 2);

            const uint32_t sAst = sbase + SM_A + (kq % 3) * A_STG;
            const uint32_t sBst = sbase + SM_B + (kq >> 1) * 2560 + (kq & 1) * 32;

            uint32_t ah[4][4];
#pragma unroll
            for (int i = 0; i < 4; i++)
                ldsm4(ah[i], sAst + aOff + (uint32_t)i * 768);   // 16 rows * 48 B
#pragma unroll
            for (int jp = 0; jp < 4; jp += 2) {
                uint32_t bb[4];
                ldsm4(bb, sBst + bOff + (uint32_t)jp * 640);     // 8 rows * 80 B
#pragma unroll
                for (int i = 0; i < 4; i++) {
                    mma16816(acc[i][jp],     ah[i], bb);
                    mma16816(acc[i][jp + 1], ah[i], bb + 2);
                }
            }
        }

        // epilogue: u[a, col] = (1/64) * sum_b C[a*32+b, col] * sU0[b, col]
        // warp w owns rows 64w..64w+63 -> a = 2w, 2w+1
#pragma unroll
        for (int ia = 0; ia < 2; ia++) {
            int a = 2 * warp + ia;
#pragma unroll
            for (int j = 0; j < 4; j++) {
                int col0 = j * 8 + c * 2;
                float p0 = 0.f, p1 = 0.f;
#pragma unroll
                for (int ih = 0; ih < 2; ih++) {
                    int i = 2 * ia + ih;
                    int b0 = ih * 16 + g, b1 = b0 + 8;
                    p0 += acc[i][j][0] * sU0[b0 * 33 + col0] + acc[i][j][2] * sU0[b1 * 33 + col0];
                    p1 += acc[i][j][1] * sU0[b0 * 33 + col0 + 1] + acc[i][j][3] * sU0[b1 * 33 + col0 + 1];
                }
#pragma unroll
                for (int off = 4; off <= 16; off <<= 1) {
                    p0 += __shfl_xor_sync(0xffffffffu, p0, off);
                    p1 += __shfl_xor_sync(0xffffffffu, p1, off);
                }
                if (g == 0) {
                    sU1[a * 33 + col0]     = p0 * UNSCALE;
                    sU1[a * 33 + col0 + 1] = p1 * UNSCALE;
                }
            }
        }
        __syncthreads();
        if (pass == 0) {
            for (int i = t; i < 32 * 33; i += 512) sU0[i] = sU1[i];
            __syncthreads();
        }
    }

    // ---- Z[o, n0+nl] = sum_a core0[o*32+a] * u1[a, nl] ----
#pragma unroll
    for (int i = 0; i < 32; i++) {
        int idx = t + i * 512;                     // 16384 core0 floats
        sXf[idx] = core0[idx];
    }
    __syncthreads();
    {
        const int nl = t & 31, oh = t >> 5;        // oh 0..15
        float u1r[32];
#pragma unroll
        for (int a = 0; a < 32; a++) u1r[a] = sU1[a * 33 + nl];
        const float4* c4 = (const float4*)sXf;
#pragma unroll 4
        for (int oo = 0; oo < 32; oo++) {
            int o = oh * 32 + oo;
            float p = 0.f;
#pragma unroll
            for (int q = 0; q < 8; q++) {
                float4 cv = c4[o * 8 + q];
                p += cv.x * u1r[q * 4]     + cv.y * u1r[q * 4 + 1]
                   + cv.z * u1r[q * 4 + 2] + cv.w * u1r[q * 4 + 3];
            }
            Z[o * NB + n0 + nl] = p;
        }
    }
}

// ---------------------------------------------------------------------------
extern "C" void kernel_launch(void* const* d_in, const int* in_sizes, int n_in,
                              void* d_out, int out_size)
{
    const float* X0    = (const float*)d_in[0];
    const float* X1    = (const float*)d_in[1];
    const float* X2    = (const float*)d_in[2];
    const float* core0 = (const float*)d_in[3];
    const float* core1 = (const float*)d_in[4];
    const float* core2 = (const float*)d_in[5];
    const float* core3 = (const float*)d_in[6];
    float* Z = (float*)d_out;

    static bool attr_done = false;
    if (!attr_done) {
        cudaFuncSetAttribute(mega_kernel,
                             cudaFuncAttributeMaxDynamicSharedMemorySize, SM_TOTAL_MEGA);
        attr_done = true;
    }

    pack_core_kernel<<<dim3(8, 16, 2), 256>>>(core1, core2);
    mega_kernel<<<128, 512, SM_TOTAL_MEGA>>>(X0, X1, X2, core0, core3, Z);
}